// round 14
// baseline (speedup 1.0000x reference)
#include <cuda_runtime.h>
#include <cuda_bf16.h>
#include <math.h>
#include <stdint.h>

#define N_ROWS 16384
#define DIM    512
#define BM     128
#define BN     128
#define BK     64
#define NSTAGE 3
#define KITERS (DIM / BK)          // 8
#define NTILE1D 8256               // 129*128/2 upper-triangle tiles

// padded smem row: 64 halves -> 72 halves (144 bytes); 144/16 = 9 == 1 mod 8
// so both cp.async STS and ldmatrix stay bank-conflict-free.
#define ROWB   144
#define STAGE_BYTES (BM * ROWB)    // 18432
#define SM_A(s) ((s) * STAGE_BYTES)
#define SM_B(s) (NSTAGE * STAGE_BYTES + (s) * STAGE_BYTES)
#define SM_TOTAL (2 * NSTAGE * STAGE_BYTES)   // 110592

// ---------------- scratch (allocation-free rule) ----------------
__device__ __align__(16) __nv_bfloat16 g_xbf[N_ROWS * DIM];   // 16 MB
__device__ unsigned long long g_best[N_ROWS];
__device__ float g_logrho[N_ROWS];
__device__ double g_partial[64];

// ---------------- helpers ----------------
__device__ __forceinline__ uint32_t smem_u32(const void* p) {
    uint32_t a;
    asm("{ .reg .u64 t; cvta.to.shared.u64 t, %1; cvt.u32.u64 %0, t; }" : "=r"(a) : "l"(p));
    return a;
}

__device__ __forceinline__ unsigned long long pack_key(float v, int idx) {
    unsigned u = __float_as_uint(v);
    u = (u & 0x80000000u) ? ~u : (u | 0x80000000u);   // order-preserving flip
    return ((unsigned long long)u << 32) | (unsigned)(~(unsigned)idx); // tie -> smaller idx
}

__device__ __forceinline__ unsigned long long shfl_xor_u64(unsigned long long k, int off) {
    return ((unsigned long long)__shfl_xor_sync(0xffffffffu, (unsigned)(k >> 32), off) << 32) |
           (unsigned)__shfl_xor_sync(0xffffffffu, (unsigned)k, off);
}

#define CP_ASYNC(sm, gm) asm volatile("cp.async.cg.shared.global [%0], [%1], 16;" :: "r"(sm), "l"(gm))
#define CP_COMMIT()      asm volatile("cp.async.commit_group;" ::: "memory")
#define CP_WAIT(n)       asm volatile("cp.async.wait_group %0;" :: "n"(n) : "memory")

#define LDSM4(r0, r1, r2, r3, addr)                                             \
    asm volatile("ldmatrix.sync.aligned.m8n8.x4.shared.b16 {%0,%1,%2,%3}, [%4];" \
                 : "=r"(r0), "=r"(r1), "=r"(r2), "=r"(r3) : "r"(addr))

#define MMA(c0, c1, c2, c3, a0, a1, a2, a3, b0, b1)                              \
    asm volatile("mma.sync.aligned.m16n8k16.row.col.f32.bf16.bf16.f32 "          \
                 "{%0,%1,%2,%3}, {%4,%5,%6,%7}, {%8,%9}, {%0,%1,%2,%3};"         \
                 : "+f"(c0), "+f"(c1), "+f"(c2), "+f"(c3)                        \
                 : "r"(a0), "r"(a1), "r"(a2), "r"(a3), "r"(b0), "r"(b1))

// ---------------- prep: fp32 -> bf16 (+ init g_best) ----------------
__global__ void prep_kernel(const float* __restrict__ x) {
    const int gid = blockIdx.x * blockDim.x + threadIdx.x;
    const int i = gid * 4;
    float4 v = *(const float4*)(x + i);
    __nv_bfloat162 a, b;
    a.x = __float2bfloat16(v.x); a.y = __float2bfloat16(v.y);
    b.x = __float2bfloat16(v.z); b.y = __float2bfloat16(v.w);
    *(__nv_bfloat162*)(g_xbf + i)     = a;
    *(__nv_bfloat162*)(g_xbf + i + 2) = b;
    if (gid < N_ROWS) g_best[gid] = 0ULL;
}

// cumulative tile count for rows < r in the upper triangle
__device__ __forceinline__ int tri_cum(int r) { return 128 * r - (r * (r - 1)) / 2; }

// ---------------- fused bf16 GEMM (mma.sync) + symmetric argmax scatter ------
// 1D grid over upper-triangle tiles (cb >= rb). Off-diagonal tiles update BOTH
// the rb-block rows (row-scan) and the cb-block rows (column-scan, symmetry).
// Inner loop software-pipelined: A fragments double-buffered per kk, B quads
// double-buffered per nb so every LDSM is covered by 4 in-flight MMAs.
__global__ __launch_bounds__(256, 2)
void nn_gemm_kernel() {
    // decode (rb, cb) from linear upper-triangle index
    const int t = blockIdx.x;
    int rb = (int)((257.0 - sqrt((double)(66049 - 8 * t))) * 0.5);
    if (rb > 127) rb = 127;
    while (tri_cum(rb + 1) <= t) rb++;
    while (tri_cum(rb) > t) rb--;
    const int cb = rb + (t - tri_cum(rb));

    extern __shared__ char smem[];
    const uint32_t sb = smem_u32(smem);

    const int tid  = threadIdx.x;
    const int lane = tid & 31;
    const int wid  = tid >> 5;
    const int warp_m = wid & 3;          // 4 row groups of 32
    const int warp_n = wid >> 2;         // 2 col groups of 64

    const __nv_bfloat16* Ag = g_xbf + (size_t)rb * BM * DIM;
    const __nv_bfloat16* Bg = g_xbf + (size_t)cb * BN * DIM;

    // cp.async mapping: row = (tid>>3) + rr*32 (rr=0..3), 16B chunk c = tid&7
    const int r0 = tid >> 3, c0 = tid & 7;

    float acc[2][8][4];
    #pragma unroll
    for (int mi = 0; mi < 2; mi++)
        #pragma unroll
        for (int ni = 0; ni < 8; ni++)
            #pragma unroll
            for (int j = 0; j < 4; j++) acc[mi][ni][j] = 0.f;

    const int lrow = (lane & 7) + ((lane >> 3) & 1) * 8;
    const uint32_t lk2 = (((lane >> 4) & 1) * 8) * 2;

    // prologue: issue stages 0, 1
    #pragma unroll
    for (int s = 0; s < NSTAGE - 1; s++) {
        const int k0 = s * BK;
        #pragma unroll
        for (int rr = 0; rr < 4; rr++) {
            CP_ASYNC(sb + SM_A(s) + (r0 + rr * 32) * ROWB + c0 * 16, Ag + (r0 + rr * 32) * DIM + k0 + c0 * 8);
            CP_ASYNC(sb + SM_B(s) + (r0 + rr * 32) * ROWB + c0 * 16, Bg + (r0 + rr * 32) * DIM + k0 + c0 * 8);
        }
        CP_COMMIT();
    }

    for (int kb = 0; kb < KITERS; kb++) {
        CP_WAIT(1);
        __syncthreads();

        if (kb + NSTAGE - 1 < KITERS) {
            const int s = (kb + NSTAGE - 1) % NSTAGE;
            const int k0 = (kb + NSTAGE - 1) * BK;
            #pragma unroll
            for (int rr = 0; rr < 4; rr++) {
                CP_ASYNC(sb + SM_A(s) + (r0 + rr * 32) * ROWB + c0 * 16, Ag + (r0 + rr * 32) * DIM + k0 + c0 * 8);
                CP_ASYNC(sb + SM_B(s) + (r0 + rr * 32) * ROWB + c0 * 16, Bg + (r0 + rr * 32) * DIM + k0 + c0 * 8);
            }
        }
        CP_COMMIT();

        const int st = kb % NSTAGE;
        const uint32_t a_base = sb + SM_A(st) + (warp_m * 32 + lrow) * ROWB + lk2;
        const uint32_t b_base = sb + SM_B(st) + (warp_n * 64 + lrow) * ROWB + lk2;

        uint32_t fa[2][8], fb[2][4];
        // prime: A pair + first B quad for kk=0
        LDSM4(fa[0][0], fa[0][1], fa[0][2], fa[0][3], a_base);
        LDSM4(fa[0][4], fa[0][5], fa[0][6], fa[0][7], a_base + 16 * ROWB);
        LDSM4(fb[0][0], fb[0][1], fb[0][2], fb[0][3], b_base);

        #pragma unroll
        for (int kk = 0; kk < 4; kk++) {           // k16 steps within BK=64; +32B per step
            const int ka = kk & 1;
            #pragma unroll
            for (int nb = 0; nb < 4; nb++) {
                const int cur = nb & 1, nxt = cur ^ 1;
                if (nb < 3) {
                    LDSM4(fb[nxt][0], fb[nxt][1], fb[nxt][2], fb[nxt][3],
                          b_base + (nb + 1) * 16 * ROWB + kk * 32);
                } else if (kk < 3) {
                    LDSM4(fa[ka ^ 1][0], fa[ka ^ 1][1], fa[ka ^ 1][2], fa[ka ^ 1][3],
                          a_base + (kk + 1) * 32);
                    LDSM4(fa[ka ^ 1][4], fa[ka ^ 1][5], fa[ka ^ 1][6], fa[ka ^ 1][7],
                          a_base + 16 * ROWB + (kk + 1) * 32);
                    LDSM4(fb[nxt][0], fb[nxt][1], fb[nxt][2], fb[nxt][3],
                          b_base + (kk + 1) * 32);
                }
                // ldmatrix x4 order: m0=n0-7/k0-7, m1=n8-15/k0-7, m2=n0-7/k8-15, m3=n8-15/k8-15
                // mma B operand = {k0-7, k8-15} of one n8 block: (q0,q2) / (q1,q3)
                MMA(acc[0][nb*2][0],   acc[0][nb*2][1],   acc[0][nb*2][2],   acc[0][nb*2][3],
                    fa[ka][0], fa[ka][1], fa[ka][2], fa[ka][3], fb[cur][0], fb[cur][2]);
                MMA(acc[0][nb*2+1][0], acc[0][nb*2+1][1], acc[0][nb*2+1][2], acc[0][nb*2+1][3],
                    fa[ka][0], fa[ka][1], fa[ka][2], fa[ka][3], fb[cur][1], fb[cur][3]);
                MMA(acc[1][nb*2][0],   acc[1][nb*2][1],   acc[1][nb*2][2],   acc[1][nb*2][3],
                    fa[ka][4], fa[ka][5], fa[ka][6], fa[ka][7], fb[cur][0], fb[cur][2]);
                MMA(acc[1][nb*2+1][0], acc[1][nb*2+1][1], acc[1][nb*2+1][2], acc[1][nb*2+1][3],
                    fa[ka][4], fa[ka][5], fa[ka][6], fa[ka][7], fb[cur][1], fb[cur][3]);
            }
        }
    }

    const int grp = lane >> 2;
    const int qc  = lane & 3;
    const bool diag = (rb == cb);

    // ---- row-scan: update rows of the rb block ----
    #pragma unroll
    for (int mi = 0; mi < 2; mi++) {
        #pragma unroll
        for (int rsel = 0; rsel < 2; rsel++) {
            const int grow = rb * BM + warp_m * 32 + mi * 16 + rsel * 8 + grp;
            unsigned long long key = 0ULL;
            #pragma unroll
            for (int ni = 0; ni < 8; ni++) {
                #pragma unroll
                for (int j = 0; j < 2; j++) {
                    const int gcol = cb * BN + warp_n * 64 + ni * 8 + qc * 2 + j;
                    if (!diag || gcol != grow) {
                        const unsigned long long k2 = pack_key(acc[mi][ni][rsel * 2 + j], gcol);
                        if (k2 > key) key = k2;
                    }
                }
            }
            #pragma unroll
            for (int off = 1; off < 4; off <<= 1) {
                const unsigned long long ok = shfl_xor_u64(key, off);
                if (ok > key) key = ok;
            }
            if (qc == 0) atomicMax(&g_best[grow], key);
        }
    }

    // ---- column-scan (symmetry): update rows of the cb block ----
    if (!diag) {
        #pragma unroll
        for (int ni = 0; ni < 8; ni++) {
            #pragma unroll
            for (int jj = 0; jj < 2; jj++) {
                unsigned long long key = 0ULL;
                #pragma unroll
                for (int mi = 0; mi < 2; mi++) {
                    #pragma unroll
                    for (int rsel = 0; rsel < 2; rsel++) {
                        const int grow = rb * BM + warp_m * 32 + mi * 16 + rsel * 8 + grp;
                        const unsigned long long k2 = pack_key(acc[mi][ni][rsel * 2 + jj], grow);
                        if (k2 > key) key = k2;
                    }
                }
                #pragma unroll
                for (int off = 4; off < 32; off <<= 1) {
                    const unsigned long long ok = shfl_xor_u64(key, off);
                    if (ok > key) key = ok;
                }
                if (grp == 0) {
                    const int gcol = cb * BN + warp_n * 64 + ni * 8 + qc * 2 + jj;
                    atomicMax(&g_best[gcol], key);
                }
            }
        }
    }
}

// ---------------- rho: warp per row, exact fp32 from original x ----------------
__global__ void rho_kernel(const float* __restrict__ x) {
    const int lane = threadIdx.x & 31;
    const int row  = blockIdx.x * 8 + (threadIdx.x >> 5);
    const unsigned long long key = g_best[row];
    const int nn = (int)(~(unsigned)(key & 0xffffffffULL));

    const float* ra = x + (size_t)row * DIM;
    const float* rbp = x + (size_t)nn * DIM;
    float s = 0.f;
    #pragma unroll
    for (int c = 0; c < 4; c++) {
        const int off = lane * 4 + c * 128;
        const float4 a = *(const float4*)(ra + off);
        const float4 b = *(const float4*)(rbp + off);
        const float d0 = a.x - b.x + 1e-6f;
        const float d1 = a.y - b.y + 1e-6f;
        const float d2 = a.z - b.z + 1e-6f;
        const float d3 = a.w - b.w + 1e-6f;
        s += d0 * d0 + d1 * d1 + d2 * d2 + d3 * d3;
    }
    #pragma unroll
    for (int off = 16; off > 0; off >>= 1)
        s += __shfl_down_sync(0xffffffffu, s, off);
    if (lane == 0) g_logrho[row] = logf(sqrtf(s) + 1e-8f);
}

// two-stage fixed-order reduction: 64 partials, then one tiny finish
__global__ void partial_kernel() {
    __shared__ double sh[256];
    const int base = blockIdx.x * 256;
    sh[threadIdx.x] = (double)g_logrho[base + threadIdx.x];
    __syncthreads();
    for (int off = 128; off > 0; off >>= 1) {
        if (threadIdx.x < off) sh[threadIdx.x] += sh[threadIdx.x + off];
        __syncthreads();
    }
    if (threadIdx.x == 0) g_partial[blockIdx.x] = sh[0];
}

__global__ void final_kernel(float* __restrict__ out) {
    if (threadIdx.x == 0) {
        double s = 0.0;
        #pragma unroll
        for (int i = 0; i < 64; i++) s += g_partial[i];
        out[0] = (float)(-s / (double)N_ROWS);
    }
}

extern "C" void kernel_launch(void* const* d_in, const int* in_sizes, int n_in,
                              void* d_out, int out_size) {
    const float* x = (const float*)d_in[0];

    cudaFuncSetAttribute(nn_gemm_kernel, cudaFuncAttributeMaxDynamicSharedMemorySize, SM_TOTAL);

    prep_kernel<<<(N_ROWS * DIM) / (256 * 4), 256>>>(x);
    nn_gemm_kernel<<<NTILE1D, 256, SM_TOTAL>>>();
    rho_kernel<<<N_ROWS / 8, 256>>>(x);
    partial_kernel<<<64, 256>>>();
    final_kernel<<<1, 32>>>((float*)d_out);
}

// round 15
// speedup vs baseline: 1.5596x; 1.5596x over previous
#include <cuda_runtime.h>
#include <cuda_bf16.h>
#include <math.h>
#include <stdint.h>

#define N_ROWS 16384
#define DIM    512
#define BM     128
#define BN     128
#define BK     64
#define NSTAGE 3
#define KITERS (DIM / BK)          // 8
#define NTILE1D 8256               // 129*128/2 upper-triangle tiles

// padded smem row: 64 halves -> 72 halves (144 bytes); 144/16 = 9 == 1 mod 8
// so both cp.async STS and ldmatrix stay bank-conflict-free.
#define ROWB   144
#define STAGE_BYTES (BM * ROWB)    // 18432
#define SM_A(s) ((s) * STAGE_BYTES)
#define SM_B(s) (NSTAGE * STAGE_BYTES + (s) * STAGE_BYTES)
#define SM_TOTAL (2 * NSTAGE * STAGE_BYTES)   // 110592

// ---------------- scratch (allocation-free rule) ----------------
__device__ __align__(16) __nv_bfloat16 g_xbf[N_ROWS * DIM];   // 16 MB
__device__ unsigned long long g_best[N_ROWS];
__device__ float g_logrho[N_ROWS];
__device__ double g_partial[64];

// ---------------- helpers ----------------
__device__ __forceinline__ uint32_t smem_u32(const void* p) {
    uint32_t a;
    asm("{ .reg .u64 t; cvta.to.shared.u64 t, %1; cvt.u32.u64 %0, t; }" : "=r"(a) : "l"(p));
    return a;
}

__device__ __forceinline__ unsigned long long pack_key(float v, int idx) {
    unsigned u = __float_as_uint(v);
    u = (u & 0x80000000u) ? ~u : (u | 0x80000000u);   // order-preserving flip
    return ((unsigned long long)u << 32) | (unsigned)(~(unsigned)idx); // tie -> smaller idx
}

__device__ __forceinline__ unsigned long long shfl_xor_u64(unsigned long long k, int off) {
    return ((unsigned long long)__shfl_xor_sync(0xffffffffu, (unsigned)(k >> 32), off) << 32) |
           (unsigned)__shfl_xor_sync(0xffffffffu, (unsigned)k, off);
}

#define CP_ASYNC(sm, gm) asm volatile("cp.async.cg.shared.global [%0], [%1], 16;" :: "r"(sm), "l"(gm))
#define CP_COMMIT()      asm volatile("cp.async.commit_group;" ::: "memory")
#define CP_WAIT(n)       asm volatile("cp.async.wait_group %0;" :: "n"(n) : "memory")

#define LDSM4(r0, r1, r2, r3, addr)                                             \
    asm volatile("ldmatrix.sync.aligned.m8n8.x4.shared.b16 {%0,%1,%2,%3}, [%4];" \
                 : "=r"(r0), "=r"(r1), "=r"(r2), "=r"(r3) : "r"(addr))

#define MMA(c0, c1, c2, c3, a0, a1, a2, a3, b0, b1)                              \
    asm volatile("mma.sync.aligned.m16n8k16.row.col.f32.bf16.bf16.f32 "          \
                 "{%0,%1,%2,%3}, {%4,%5,%6,%7}, {%8,%9}, {%0,%1,%2,%3};"         \
                 : "+f"(c0), "+f"(c1), "+f"(c2), "+f"(c3)                        \
                 : "r"(a0), "r"(a1), "r"(a2), "r"(a3), "r"(b0), "r"(b1))

// ---------------- prep: fp32 -> bf16 (+ init g_best) ----------------
__global__ void prep_kernel(const float* __restrict__ x) {
    const int gid = blockIdx.x * blockDim.x + threadIdx.x;
    const int i = gid * 4;
    float4 v = *(const float4*)(x + i);
    __nv_bfloat162 a, b;
    a.x = __float2bfloat16(v.x); a.y = __float2bfloat16(v.y);
    b.x = __float2bfloat16(v.z); b.y = __float2bfloat16(v.w);
    *(__nv_bfloat162*)(g_xbf + i)     = a;
    *(__nv_bfloat162*)(g_xbf + i + 2) = b;
    if (gid < N_ROWS) g_best[gid] = 0ULL;
}

// cumulative tile count for rows < r in the upper triangle
__device__ __forceinline__ int tri_cum(int r) { return 128 * r - (r * (r - 1)) / 2; }

// ---------------- fused bf16 GEMM (mma.sync) + symmetric argmax scatter ------
// 1D grid over upper-triangle tiles (cb >= rb). Off-diagonal tiles update BOTH
// the rb-block rows (row-scan) and the cb-block rows (column-scan, symmetry).
// Inner loop: flat order — all 6 LDSM issued up front, then 16 MMAs (empirically
// best; hand software-pipelining regressed, see R14 post-mortem).
__global__ __launch_bounds__(256, 2)
void nn_gemm_kernel() {
    // decode (rb, cb) from linear upper-triangle index
    const int t = blockIdx.x;
    int rb = (int)((257.0 - sqrt((double)(66049 - 8 * t))) * 0.5);
    if (rb > 127) rb = 127;
    while (tri_cum(rb + 1) <= t) rb++;
    while (tri_cum(rb) > t) rb--;
    const int cb = rb + (t - tri_cum(rb));

    extern __shared__ char smem[];
    const uint32_t sb = smem_u32(smem);

    const int tid  = threadIdx.x;
    const int lane = tid & 31;
    const int wid  = tid >> 5;
    const int warp_m = wid & 3;          // 4 row groups of 32
    const int warp_n = wid >> 2;         // 2 col groups of 64

    const __nv_bfloat16* Ag = g_xbf + (size_t)rb * BM * DIM;
    const __nv_bfloat16* Bg = g_xbf + (size_t)cb * BN * DIM;

    // cp.async mapping: row = (tid>>3) + rr*32 (rr=0..3), 16B chunk c = tid&7
    const int r0 = tid >> 3, c0 = tid & 7;

    float acc[2][8][4];
    #pragma unroll
    for (int mi = 0; mi < 2; mi++)
        #pragma unroll
        for (int ni = 0; ni < 8; ni++)
            #pragma unroll
            for (int j = 0; j < 4; j++) acc[mi][ni][j] = 0.f;

    const int lrow = (lane & 7) + ((lane >> 3) & 1) * 8;
    const int lkof = ((lane >> 4) & 1) * 8;

    // prologue: issue stages 0, 1
    #pragma unroll
    for (int s = 0; s < NSTAGE - 1; s++) {
        const int k0 = s * BK;
        #pragma unroll
        for (int rr = 0; rr < 4; rr++) {
            CP_ASYNC(sb + SM_A(s) + (r0 + rr * 32) * ROWB + c0 * 16, Ag + (r0 + rr * 32) * DIM + k0 + c0 * 8);
            CP_ASYNC(sb + SM_B(s) + (r0 + rr * 32) * ROWB + c0 * 16, Bg + (r0 + rr * 32) * DIM + k0 + c0 * 8);
        }
        CP_COMMIT();
    }

    for (int kb = 0; kb < KITERS; kb++) {
        CP_WAIT(1);
        __syncthreads();   // single barrier per kb

        if (kb + NSTAGE - 1 < KITERS) {
            const int s = (kb + NSTAGE - 1) % NSTAGE;
            const int k0 = (kb + NSTAGE - 1) * BK;
            #pragma unroll
            for (int rr = 0; rr < 4; rr++) {
                CP_ASYNC(sb + SM_A(s) + (r0 + rr * 32) * ROWB + c0 * 16, Ag + (r0 + rr * 32) * DIM + k0 + c0 * 8);
                CP_ASYNC(sb + SM_B(s) + (r0 + rr * 32) * ROWB + c0 * 16, Bg + (r0 + rr * 32) * DIM + k0 + c0 * 8);
            }
        }
        CP_COMMIT();

        const int st = kb % NSTAGE;
        const uint32_t a_base = sb + SM_A(st) + (warp_m * 32 + lrow) * ROWB;
        const uint32_t b_base = sb + SM_B(st) + (warp_n * 64 + lrow) * ROWB;

        #pragma unroll
        for (int kk = 0; kk < BK; kk += 16) {
            const uint32_t koff = (kk + lkof) * 2;
            uint32_t a0[4], a1[4], b[4][4];
            LDSM4(a0[0], a0[1], a0[2], a0[3], a_base + koff);
            LDSM4(a1[0], a1[1], a1[2], a1[3], a_base + 16 * ROWB + koff);
            #pragma unroll
            for (int nb = 0; nb < 4; nb++)
                LDSM4(b[nb][0], b[nb][1], b[nb][2], b[nb][3], b_base + nb * 16 * ROWB + koff);

            // ldmatrix x4 order: m0=n0-7/k0-7, m1=n8-15/k0-7, m2=n0-7/k8-15, m3=n8-15/k8-15
            // mma B operand = {k0-7, k8-15} of one n8 block: (reg0,reg2) / (reg1,reg3)
            #pragma unroll
            for (int nb = 0; nb < 4; nb++) {
                MMA(acc[0][nb*2][0],   acc[0][nb*2][1],   acc[0][nb*2][2],   acc[0][nb*2][3],
                    a0[0], a0[1], a0[2], a0[3], b[nb][0], b[nb][2]);
                MMA(acc[0][nb*2+1][0], acc[0][nb*2+1][1], acc[0][nb*2+1][2], acc[0][nb*2+1][3],
                    a0[0], a0[1], a0[2], a0[3], b[nb][1], b[nb][3]);
                MMA(acc[1][nb*2][0],   acc[1][nb*2][1],   acc[1][nb*2][2],   acc[1][nb*2][3],
                    a1[0], a1[1], a1[2], a1[3], b[nb][0], b[nb][2]);
                MMA(acc[1][nb*2+1][0], acc[1][nb*2+1][1], acc[1][nb*2+1][2], acc[1][nb*2+1][3],
                    a1[0], a1[1], a1[2], a1[3], b[nb][1], b[nb][3]);
            }
        }
    }

    const int grp = lane >> 2;
    const int qc  = lane & 3;
    const bool diag = (rb == cb);

    // ---- row-scan: update rows of the rb block ----
    #pragma unroll
    for (int mi = 0; mi < 2; mi++) {
        #pragma unroll
        for (int rsel = 0; rsel < 2; rsel++) {
            const int grow = rb * BM + warp_m * 32 + mi * 16 + rsel * 8 + grp;
            unsigned long long key = 0ULL;
            #pragma unroll
            for (int ni = 0; ni < 8; ni++) {
                #pragma unroll
                for (int j = 0; j < 2; j++) {
                    const int gcol = cb * BN + warp_n * 64 + ni * 8 + qc * 2 + j;
                    if (!diag || gcol != grow) {
                        const unsigned long long k2 = pack_key(acc[mi][ni][rsel * 2 + j], gcol);
                        if (k2 > key) key = k2;
                    }
                }
            }
            #pragma unroll
            for (int off = 1; off < 4; off <<= 1) {
                const unsigned long long ok = shfl_xor_u64(key, off);
                if (ok > key) key = ok;
            }
            if (qc == 0) atomicMax(&g_best[grow], key);
        }
    }

    // ---- column-scan (symmetry): update rows of the cb block ----
    if (!diag) {
        #pragma unroll
        for (int ni = 0; ni < 8; ni++) {
            #pragma unroll
            for (int jj = 0; jj < 2; jj++) {
                unsigned long long key = 0ULL;
                #pragma unroll
                for (int mi = 0; mi < 2; mi++) {
                    #pragma unroll
                    for (int rsel = 0; rsel < 2; rsel++) {
                        const int grow = rb * BM + warp_m * 32 + mi * 16 + rsel * 8 + grp;
                        const unsigned long long k2 = pack_key(acc[mi][ni][rsel * 2 + jj], grow);
                        if (k2 > key) key = k2;
                    }
                }
                #pragma unroll
                for (int off = 4; off < 32; off <<= 1) {
                    const unsigned long long ok = shfl_xor_u64(key, off);
                    if (ok > key) key = ok;
                }
                if (grp == 0) {
                    const int gcol = cb * BN + warp_n * 64 + ni * 8 + qc * 2 + jj;
                    atomicMax(&g_best[gcol], key);
                }
            }
        }
    }
}

// ---------------- rho: warp per row, exact fp32 from original x ----------------
__global__ void rho_kernel(const float* __restrict__ x) {
    const int lane = threadIdx.x & 31;
    const int row  = blockIdx.x * 8 + (threadIdx.x >> 5);
    const unsigned long long key = g_best[row];
    const int nn = (int)(~(unsigned)(key & 0xffffffffULL));

    const float* ra  = x + (size_t)row * DIM;
    const float* rbp = x + (size_t)nn * DIM;
    float s = 0.f;
    #pragma unroll
    for (int c = 0; c < 4; c++) {
        const int off = lane * 4 + c * 128;
        const float4 a = *(const float4*)(ra + off);
        const float4 b = *(const float4*)(rbp + off);
        const float d0 = a.x - b.x + 1e-6f;
        const float d1 = a.y - b.y + 1e-6f;
        const float d2 = a.z - b.z + 1e-6f;
        const float d3 = a.w - b.w + 1e-6f;
        s += d0 * d0 + d1 * d1 + d2 * d2 + d3 * d3;
    }
    #pragma unroll
    for (int off = 16; off > 0; off >>= 1)
        s += __shfl_down_sync(0xffffffffu, s, off);
    if (lane == 0) g_logrho[row] = logf(sqrtf(s) + 1e-8f);
}

// two-stage fixed-order reduction: 64 partials, then one tiny finish
__global__ void partial_kernel() {
    __shared__ double sh[256];
    const int base = blockIdx.x * 256;
    sh[threadIdx.x] = (double)g_logrho[base + threadIdx.x];
    __syncthreads();
    for (int off = 128; off > 0; off >>= 1) {
        if (threadIdx.x < off) sh[threadIdx.x] += sh[threadIdx.x + off];
        __syncthreads();
    }
    if (threadIdx.x == 0) g_partial[blockIdx.x] = sh[0];
}

__global__ void final_kernel(float* __restrict__ out) {
    if (threadIdx.x == 0) {
        double s = 0.0;
        #pragma unroll
        for (int i = 0; i < 64; i++) s += g_partial[i];
        out[0] = (float)(-s / (double)N_ROWS);
    }
}

extern "C" void kernel_launch(void* const* d_in, const int* in_sizes, int n_in,
                              void* d_out, int out_size) {
    const float* x = (const float*)d_in[0];

    cudaFuncSetAttribute(nn_gemm_kernel, cudaFuncAttributeMaxDynamicSharedMemorySize, SM_TOTAL);

    prep_kernel<<<(N_ROWS * DIM) / (256 * 4), 256>>>(x);
    nn_gemm_kernel<<<NTILE1D, 256, SM_TOTAL>>>();
    rho_kernel<<<N_ROWS / 8, 256>>>(x);
    partial_kernel<<<64, 256>>>();
    final_kernel<<<1, 32>>>((float*)d_out);
}